// round 16
// baseline (speedup 1.0000x reference)
#include <cuda_runtime.h>
#include <cuda_bf16.h>
#include <cstdint>

// Loss_Labels: -mean over B of ( label==1 ? log_softmax(s,a)[0]
//                              : label==2 ? log_softmax(s,a)[1] : 0 )
//
// Labels int32 on device. 12 B/element, ~100 MB streamed.
// R16 = R15 (pair body w/ 6 front-batched 128-bit loads, shuffle epilogue,
// flat finalize w/ float4 partial reads) at NT=512 / OCC=4 (grid 592, same
// 2048 thr/SM, one wave). NB=592 partials -> 148 float4 reads over 512
// threads = ONE parallel L2 round in the finalize (was 2), half the
// arrivals. Fixed lane/warp order everywhere -> deterministic.

#define NSM 148
#define OCC 4
#define NB (NSM * OCC)   // 592 blocks: one full wave at 4 blocks/SM
#define NT 512
#define NWARP (NT / 32)

__device__ float g_partials[NB];
__device__ unsigned int g_done_count;   // zero-init; reset by last block

__device__ __forceinline__ float err_term(float s, float a, int lab) {
    // d = a - s; lse - s = max(d,0) + log(1 + exp(-|d|))  (arg in (1,2])
    float d = a - s;
    float t = fmaxf(d, 0.0f) + __logf(1.0f + __expf(-fabsf(d)));
    return (lab == 1) ? -t : ((lab == 2) ? (d - t) : 0.0f);
}

// Deterministic block reduction: warp shuffle + one smem pass + warp0 shuffle.
// Result valid in thread 0. One __syncthreads total.
__device__ __forceinline__ float block_reduce(float v, float* smw) {
    const int lane = threadIdx.x & 31;
    const int wid  = threadIdx.x >> 5;
#pragma unroll
    for (int off = 16; off > 0; off >>= 1)
        v += __shfl_down_sync(0xffffffffu, v, off);
    if (lane == 0) smw[wid] = v;
    __syncthreads();
    if (wid == 0) {
        v = (lane < NWARP) ? smw[lane] : 0.0f;
#pragma unroll
        for (int off = NWARP / 2; off > 0; off >>= 1)
            v += __shfl_down_sync(0xffffffffu, v, off);
    }
    return v;
}

__global__ void __launch_bounds__(NT, OCC)
loss_fused_kernel(const float4* __restrict__ s4,
                  const float4* __restrict__ a4,
                  const int4*   __restrict__ l4,
                  float* __restrict__ out,
                  int n, int nvec)
{
    const int npair  = nvec / 2;               // pairs of float4
    const int stride = gridDim.x * blockDim.x;

    float acc = 0.0f;
    for (int i = blockIdx.x * blockDim.x + threadIdx.x; i < npair; i += stride) {
        // 6 independent 128-bit loads, front-batched
        float4 s0 = s4[2 * i];
        float4 s1 = s4[2 * i + 1];
        float4 a0 = a4[2 * i];
        float4 a1 = a4[2 * i + 1];
        int4   l0 = l4[2 * i];
        int4   l1 = l4[2 * i + 1];

        acc += err_term(s0.x, a0.x, l0.x);
        acc += err_term(s0.y, a0.y, l0.y);
        acc += err_term(s0.z, a0.z, l0.z);
        acc += err_term(s0.w, a0.w, l0.w);
        acc += err_term(s1.x, a1.x, l1.x);
        acc += err_term(s1.y, a1.y, l1.y);
        acc += err_term(s1.z, a1.z, l1.z);
        acc += err_term(s1.w, a1.w, l1.w);
    }

    // scalar tail: [npair*8, n) (empty for n = 8388608; kept for safety)
    if (blockIdx.x == 0) {
        const float* s = (const float*)s4;
        const float* a = (const float*)a4;
        const int*   l = (const int*)l4;
        for (int t = npair * 8 + threadIdx.x; t < n; t += NT)
            acc += err_term(s[t], a[t], l[t]);
    }

    __shared__ float smw[NWARP];
    float bsum = block_reduce(acc, smw);

    __shared__ bool s_last;
    if (threadIdx.x == 0) {
        g_partials[blockIdx.x] = bsum;
        __threadfence();
        unsigned int prev = atomicAdd(&g_done_count, 1u);
        s_last = (prev == (unsigned int)(gridDim.x - 1));
    }
    __syncthreads();

    if (s_last) {
        __threadfence();  // all partials visible
        // vectorized partial read: NB/4 = 148 float4s over 512 threads
        // -> one parallel L2 round.
        float facc = 0.0f;
        const float4* p4 = (const float4*)g_partials;
        if (threadIdx.x < NB / 4) {
            float4 p = p4[threadIdx.x];
            facc = (p.x + p.y) + (p.z + p.w);
        }
        __syncthreads();
        float total = block_reduce(facc, smw);
        if (threadIdx.x == 0) {
            out[0] = -total / (float)n;
            g_done_count = 0;   // reset for next graph replay
        }
    }
}

extern "C" void kernel_launch(void* const* d_in, const int* in_sizes, int n_in,
                              void* d_out, int out_size)
{
    const float* s   = (const float*)d_in[0];  // synonymy_score [B]
    const float* a   = (const float*)d_in[1];  // antonymy_score [B]
    const int*   lab = (const int*)d_in[2];    // labels [B] (int32 on device)
    float*       out = (float*)d_out;

    const int n    = in_sizes[0];
    const int nvec = n / 4;

    loss_fused_kernel<<<NB, NT>>>((const float4*)s, (const float4*)a,
                                  (const int4*)lab, out, n, nvec);
}

// round 17
// speedup vs baseline: 1.0038x; 1.0038x over previous
#include <cuda_runtime.h>
#include <cuda_bf16.h>
#include <cstdint>

// Loss_Labels: -mean over B of ( label==1 ? log_softmax(s,a)[0]
//                              : label==2 ? log_softmax(s,a)[1] : 0 )
//
// Labels int32 on device. 12 B/element, ~100 MB streamed.
// R17 = R16 (pair body w/ 6 front-batched 128-bit loads, shuffle epilogue,
// flat finalize w/ float4 partial reads) at NT=1024 / OCC=2 (grid 296 =
// one wave, same 2048 thr/SM). 296 partials -> 74 float4 reads in one
// parallel round; 296 arrivals. Fixed order everywhere -> deterministic.

#define NSM 148
#define OCC 2
#define NB (NSM * OCC)   // 296 blocks: one full wave at 2 blocks/SM
#define NT 1024
#define NWARP (NT / 32)  // 32

__device__ float g_partials[NB];
__device__ unsigned int g_done_count;   // zero-init; reset by last block

__device__ __forceinline__ float err_term(float s, float a, int lab) {
    // d = a - s; lse - s = max(d,0) + log(1 + exp(-|d|))  (arg in (1,2])
    float d = a - s;
    float t = fmaxf(d, 0.0f) + __logf(1.0f + __expf(-fabsf(d)));
    return (lab == 1) ? -t : ((lab == 2) ? (d - t) : 0.0f);
}

// Deterministic block reduction: warp shuffle + one smem pass + warp0 shuffle.
// Result valid in thread 0. One __syncthreads total.
__device__ __forceinline__ float block_reduce(float v, float* smw) {
    const int lane = threadIdx.x & 31;
    const int wid  = threadIdx.x >> 5;
#pragma unroll
    for (int off = 16; off > 0; off >>= 1)
        v += __shfl_down_sync(0xffffffffu, v, off);
    if (lane == 0) smw[wid] = v;
    __syncthreads();
    if (wid == 0) {
        v = (lane < NWARP) ? smw[lane] : 0.0f;
#pragma unroll
        for (int off = NWARP / 2; off > 0; off >>= 1)
            v += __shfl_down_sync(0xffffffffu, v, off);
    }
    return v;
}

__global__ void __launch_bounds__(NT, OCC)
loss_fused_kernel(const float4* __restrict__ s4,
                  const float4* __restrict__ a4,
                  const int4*   __restrict__ l4,
                  float* __restrict__ out,
                  int n, int nvec)
{
    const int npair  = nvec / 2;               // pairs of float4
    const int stride = gridDim.x * blockDim.x;

    float acc = 0.0f;
    for (int i = blockIdx.x * blockDim.x + threadIdx.x; i < npair; i += stride) {
        // 6 independent 128-bit loads, front-batched
        float4 s0 = s4[2 * i];
        float4 s1 = s4[2 * i + 1];
        float4 a0 = a4[2 * i];
        float4 a1 = a4[2 * i + 1];
        int4   l0 = l4[2 * i];
        int4   l1 = l4[2 * i + 1];

        acc += err_term(s0.x, a0.x, l0.x);
        acc += err_term(s0.y, a0.y, l0.y);
        acc += err_term(s0.z, a0.z, l0.z);
        acc += err_term(s0.w, a0.w, l0.w);
        acc += err_term(s1.x, a1.x, l1.x);
        acc += err_term(s1.y, a1.y, l1.y);
        acc += err_term(s1.z, a1.z, l1.z);
        acc += err_term(s1.w, a1.w, l1.w);
    }

    // scalar tail: [npair*8, n) (empty for n = 8388608; kept for safety)
    if (blockIdx.x == 0) {
        const float* s = (const float*)s4;
        const float* a = (const float*)a4;
        const int*   l = (const int*)l4;
        for (int t = npair * 8 + threadIdx.x; t < n; t += NT)
            acc += err_term(s[t], a[t], l[t]);
    }

    __shared__ float smw[NWARP];
    float bsum = block_reduce(acc, smw);

    __shared__ bool s_last;
    if (threadIdx.x == 0) {
        g_partials[blockIdx.x] = bsum;
        __threadfence();
        unsigned int prev = atomicAdd(&g_done_count, 1u);
        s_last = (prev == (unsigned int)(gridDim.x - 1));
    }
    __syncthreads();

    if (s_last) {
        __threadfence();  // all partials visible
        // vectorized partial read: NB/4 = 74 float4s, one parallel round
        float facc = 0.0f;
        const float4* p4 = (const float4*)g_partials;
        if (threadIdx.x < NB / 4) {
            float4 p = p4[threadIdx.x];
            facc = (p.x + p.y) + (p.z + p.w);
        }
        __syncthreads();
        float total = block_reduce(facc, smw);
        if (threadIdx.x == 0) {
            out[0] = -total / (float)n;
            g_done_count = 0;   // reset for next graph replay
        }
    }
}

extern "C" void kernel_launch(void* const* d_in, const int* in_sizes, int n_in,
                              void* d_out, int out_size)
{
    const float* s   = (const float*)d_in[0];  // synonymy_score [B]
    const float* a   = (const float*)d_in[1];  // antonymy_score [B]
    const int*   lab = (const int*)d_in[2];    // labels [B] (int32 on device)
    float*       out = (float*)d_out;

    const int n    = in_sizes[0];
    const int nvec = n / 4;

    loss_fused_kernel<<<NB, NT>>>((const float4*)s, (const float4*)a,
                                  (const int4*)lab, out, n, nvec);
}